// round 7
// baseline (speedup 1.0000x reference)
#include <cuda_runtime.h>
#include <cuda_fp16.h>
#include <math.h>

// ---------------- dims ----------------
#define BB    8
#define NNODE 1024
#define DD    256
#define HH    8
#define DHH   32
#define DFFX  1024
#define LGN   2
#define LTN   2
#define NBCAP 256
#define MTOT  (BB*NNODE)

// ---------------- scratch (device globals; no runtime allocation) ----------------
__device__ float                 g_XC[MTOT*DD];
__device__ __align__(16) __half  g_XCH[MTOT*DD];
__device__ __align__(16) __half  g_EMBH[MTOT*DD];
__device__ __align__(16) __half  g_HBH[MTOT*HH*DD];
__device__ __align__(16) signed char g_HQ[MTOT*HH*DD];   // int8 GAT features
__device__ float                 g_HS[MTOT*HH];          // per (node,head) scale
__device__ float                 g_AS[MTOT*HH];
__device__ float                 g_AD[MTOT*HH];
__device__ float                 g_ASP[32*MTOT];
__device__ float                 g_ADP[32*MTOT];
__device__ __align__(16) __half  g_QKVH[MTOT*3*DD];
__device__ __align__(16) __half  g_WQKVH[LTN*DD*3*DD];
__device__ float                 g_BQKV[LTN*3*DD];
__device__ __align__(16) __half  g_GATWH[LGN*HH*DD*DD];
__device__ __align__(16) __half  g_WOH[LTN*DD*DD];
__device__ __align__(16) __half  g_W1H[LTN*DD*DFFX];
__device__ __align__(16) __half  g_W2H[LTN*DFFX*DD];
__device__ __align__(16) __half  g_AOH[MTOT*DD];
__device__ float                 g_Y [MTOT*DD];
__device__ __align__(16) __half  g_YH[MTOT*DD];
__device__ __align__(16) __half  g_FFH[MTOT*DFFX];
__device__ unsigned              g_BITS[MTOT*(NNODE/32)];
__device__ int                   g_NBR[MTOT*NBCAP];
__device__ int                   g_CNT[MTOT];

// ---------------- helpers ----------------
__device__ __forceinline__ void mma_f16(float* c, const unsigned* a, const unsigned* b) {
    asm volatile(
        "mma.sync.aligned.m16n8k16.row.col.f32.f16.f16.f32 "
        "{%0,%1,%2,%3}, {%4,%5,%6,%7}, {%8,%9}, {%0,%1,%2,%3};\n"
        : "+f"(c[0]), "+f"(c[1]), "+f"(c[2]), "+f"(c[3])
        : "r"(a[0]), "r"(a[1]), "r"(a[2]), "r"(a[3]), "r"(b[0]), "r"(b[1]));
}

__device__ __forceinline__ unsigned saddr(const void* p) {
    return (unsigned)__cvta_generic_to_shared(p);
}
__device__ __forceinline__ void cp16(unsigned dst, const void* src) {
    asm volatile("cp.async.cg.shared.global [%0], [%1], 16;\n" :: "r"(dst), "l"(src));
}
__device__ __forceinline__ void cp_commit() {
    asm volatile("cp.async.commit_group;\n" ::: "memory");
}
template<int N>
__device__ __forceinline__ void cp_wait() {
    asm volatile("cp.async.wait_group %0;\n" :: "n"(N) : "memory");
}
__device__ __forceinline__ void ldsm4(unsigned& r0, unsigned& r1, unsigned& r2, unsigned& r3,
                                      unsigned addr) {
    asm volatile("ldmatrix.sync.aligned.m8n8.x4.shared.b16 {%0,%1,%2,%3}, [%4];"
                 : "=r"(r0), "=r"(r1), "=r"(r2), "=r"(r3) : "r"(addr));
}
__device__ __forceinline__ void ldsm4t(unsigned& r0, unsigned& r1, unsigned& r2, unsigned& r3,
                                       unsigned addr) {
    asm volatile("ldmatrix.sync.aligned.m8n8.x4.trans.shared.b16 {%0,%1,%2,%3}, [%4];"
                 : "=r"(r0), "=r"(r1), "=r"(r2), "=r"(r3) : "r"(addr));
}

// ---------------- adjacency pack ----------------
__global__ void pack_adj_k(const int* __restrict__ mask, unsigned* __restrict__ bits) {
    int idx = blockIdx.x * blockDim.x + threadIdx.x;
    int t  = idx & (NNODE - 1);
    int sw = (idx >> 10) & 31;
    int b  = idx >> 15;
    const int* mp = mask + ((size_t)b * NNODE + (size_t)sw * 32) * NNODE + t;
    unsigned w = 0;
    #pragma unroll
    for (int i = 0; i < 32; i++)
        if (mp[(size_t)i * NNODE] > 0) w |= (1u << i);
    int s0 = sw * 32;
    if (t >= s0 && t < s0 + 32) w |= (1u << (t - s0));
    bits[(b * NNODE + t) * 32 + sw] = w;
}

// ---------------- neighbor list build ----------------
__global__ void build_nbr_k(const unsigned* __restrict__ bits,
                            int* __restrict__ nbr, int* __restrict__ cnt) {
    int bt = blockIdx.x * blockDim.x + threadIdx.x;
    if (bt >= MTOT) return;
    const unsigned* bw = bits + (size_t)bt * 32;
    int* np = nbr + (size_t)bt * NBCAP;
    int c = 0;
    #pragma unroll 4
    for (int w = 0; w < 32; w++) {
        unsigned m = bw[w];
        while (m) {
            int bit = __ffs(m) - 1;
            m &= m - 1;
            if (c < NBCAP) np[c] = w * 32 + bit;
            c++;
        }
    }
    cnt[bt] = c < NBCAP ? c : NBCAP;
}

// ---------------- generic fp32 -> fp16 convert ----------------
__global__ void cvt_half_k(const float* __restrict__ src, __half* __restrict__ dst, int n) {
    int i = blockIdx.x * 256 + threadIdx.x;
    if (i * 4 >= n) return;
    float4 v = *(const float4*)(src + i * 4);
    *(__half2*)(dst + i * 4)     = __floats2half2_rn(v.x, v.y);
    *(__half2*)(dst + i * 4 + 2) = __floats2half2_rn(v.z, v.w);
}

// ---------------- QKV pack ----------------
__global__ void pack_qkv_k(const float* __restrict__ Wq, const float* __restrict__ Wk,
                           const float* __restrict__ Wv, const float* __restrict__ bq,
                           const float* __restrict__ bk, const float* __restrict__ bv,
                           __half* __restrict__ W, float* __restrict__ Bb)
{
    int idx = blockIdx.x * 256 + threadIdx.x;
    if (idx >= LTN * DD * 3 * DD) return;
    int n = idx % (3 * DD);
    int k = (idx / (3 * DD)) % DD;
    int l = idx / (3 * DD * DD);
    float v;
    if (n < DD)            v = Wq[((size_t)l * DD + k) * DD + n];
    else if (n < 2 * DD)   v = Wk[((size_t)l * DD + k) * DD + n - DD];
    else                   v = Wv[((size_t)l * DD + k) * DD + n - 2 * DD];
    W[idx] = __float2half_rn(v);
    if (k == 0) {
        float bvv;
        if (n < DD)          bvv = bq[l * DD + n];
        else if (n < 2 * DD) bvv = bk[l * DD + n - DD];
        else                 bvv = bv[l * DD + n - 2 * DD];
        Bb[l * 3 * DD + n] = bvv;
    }
}

// ---------------- fp16 tensor-core GEMM: cp.async + ldmatrix ----------------
template<bool BT, int ACT, int HALF_OUT, int ASAD>
__global__ void __launch_bounds__(256) hgemm_k(
    int M, int Ncol, int K,
    const __half* __restrict__ A, int lda,
    const __half* __restrict__ B, int ldb,
    void* __restrict__ Cv, int ldc,
    const float* __restrict__ bias,
    const float* __restrict__ attS, const float* __restrict__ attD,
    float* __restrict__ ASP, float* __restrict__ ADP)
{
    __shared__ __align__(16) __half sA[2][128 * 24];
    __shared__ __align__(16) __half sB[2][3072];
    const int tid  = threadIdx.x;
    const int lane = tid & 31, wid = tid >> 5;
    const int wm = wid & 3, wn = wid >> 2;
    const int m0 = blockIdx.y * 128, n0 = blockIdx.x * 128;
    const int r = lane >> 2, cq = lane & 3;

    float acc[2][8][4];
    #pragma unroll
    for (int mt = 0; mt < 2; mt++)
        #pragma unroll
        for (int nt = 0; nt < 8; nt++)
            #pragma unroll
            for (int u = 0; u < 4; u++) acc[mt][nt][u] = 0.f;

    const int T = K / 16;

    auto loadT = [&](int st, int k0) {
        {
            int m = tid >> 1, c = tid & 1;
            cp16(saddr(&sA[st][m * 24 + c * 8]), A + (size_t)(m0 + m) * lda + k0 + c * 8);
        }
        if (BT) {
            int n = tid >> 1, c = tid & 1;
            cp16(saddr(&sB[st][n * 24 + c * 8]), B + (size_t)(n0 + n) * ldb + k0 + c * 8);
        } else {
            int kk = tid >> 4, c = tid & 15;
            cp16(saddr(&sB[st][kk * 136 + c * 8]), B + (size_t)(k0 + kk) * ldb + n0 + c * 8);
        }
        cp_commit();
    };

    loadT(0, 0);
    for (int t = 0; t < T; t++) {
        if (t + 1 < T) { loadT((t + 1) & 1, (t + 1) * 16); cp_wait<1>(); }
        else           { cp_wait<0>(); }
        __syncthreads();
        const int st = t & 1;

        unsigned af[2][4], bf[8][2];
        #pragma unroll
        for (int mt = 0; mt < 2; mt++) {
            int mrow = wm * 32 + mt * 16;
            unsigned addr = saddr(&sA[st][(mrow + (lane & 15)) * 24 + (lane >> 4) * 8]);
            ldsm4(af[mt][0], af[mt][1], af[mt][2], af[mt][3], addr);
        }
        #pragma unroll
        for (int p = 0; p < 4; p++) {
            int nb = wn * 64 + p * 16;
            if (BT) {
                int row = nb + (lane & 7) + ((lane >> 4) << 3);
                int col = ((lane >> 3) & 1) * 8;
                unsigned addr = saddr(&sB[st][row * 24 + col]);
                ldsm4(bf[2 * p][0], bf[2 * p][1], bf[2 * p + 1][0], bf[2 * p + 1][1], addr);
            } else {
                int krow = (lane & 7) + (((lane >> 3) & 1) << 3);
                int coln = nb + (lane >> 4) * 8;
                unsigned addr = saddr(&sB[st][krow * 136 + coln]);
                ldsm4t(bf[2 * p][0], bf[2 * p][1], bf[2 * p + 1][0], bf[2 * p + 1][1], addr);
            }
        }
        #pragma unroll
        for (int mt = 0; mt < 2; mt++)
            #pragma unroll
            for (int nt = 0; nt < 8; nt++)
                mma_f16(acc[mt][nt], af[mt], bf[nt]);
        __syncthreads();
    }

    if (ASAD) {
        float sS[2][2] = {{0,0},{0,0}}, sD[2][2] = {{0,0},{0,0}};
        #pragma unroll
        for (int mt = 0; mt < 2; mt++)
            #pragma unroll
            for (int nt = 0; nt < 8; nt++)
                #pragma unroll
                for (int u = 0; u < 4; u++) {
                    int g = n0 + wn * 64 + nt * 8 + cq * 2 + (u & 1);
                    float v = acc[mt][nt][u];
                    sS[mt][u >> 1] += v * attS[g];
                    sD[mt][u >> 1] += v * attD[g];
                }
        #pragma unroll
        for (int o = 1; o <= 2; o <<= 1)
            #pragma unroll
            for (int mt = 0; mt < 2; mt++)
                #pragma unroll
                for (int q = 0; q < 2; q++) {
                    sS[mt][q] += __shfl_xor_sync(0xffffffffu, sS[mt][q], o);
                    sD[mt][q] += __shfl_xor_sync(0xffffffffu, sD[mt][q], o);
                }
        if (cq == 0) {
            int j = (n0 >> 6) + wn;
            #pragma unroll
            for (int mt = 0; mt < 2; mt++)
                #pragma unroll
                for (int q = 0; q < 2; q++) {
                    int row = m0 + wm * 32 + mt * 16 + r + q * 8;
                    ASP[(size_t)j * M + row] = sS[mt][q];
                    ADP[(size_t)j * M + row] = sD[mt][q];
                }
        }
    }

    #pragma unroll
    for (int mt = 0; mt < 2; mt++) {
        int mrow = m0 + wm * 32 + mt * 16 + r;
        #pragma unroll
        for (int nt = 0; nt < 8; nt++) {
            int ncol = n0 + wn * 64 + nt * 8 + cq * 2;
            float* ac = acc[mt][nt];
            float2 v0 = make_float2(ac[0], ac[1]);
            float2 v1 = make_float2(ac[2], ac[3]);
            if (bias) {
                float b0 = bias[ncol], b1 = bias[ncol + 1];
                v0.x += b0; v0.y += b1; v1.x += b0; v1.y += b1;
            }
            if (ACT == 1) {
                v0.x = fmaxf(v0.x, 0.f); v0.y = fmaxf(v0.y, 0.f);
                v1.x = fmaxf(v1.x, 0.f); v1.y = fmaxf(v1.y, 0.f);
            }
            if (HALF_OUT) {
                __half* Ch = (__half*)Cv;
                *(__half2*)(Ch + (size_t)mrow * ldc + ncol) = __floats2half2_rn(v0.x, v0.y);
                *(__half2*)(Ch + (size_t)(mrow + 8) * ldc + ncol) = __floats2half2_rn(v1.x, v1.y);
            } else {
                float* Cf = (float*)Cv;
                *(float2*)(Cf + (size_t)mrow * ldc + ncol) = v0;
                *(float2*)(Cf + (size_t)(mrow + 8) * ldc + ncol) = v1;
            }
        }
    }
}

// ---------------- asad reduce ----------------
__global__ void asad_reduce_k(const float* __restrict__ ASP, const float* __restrict__ ADP,
                              float* __restrict__ as_, float* __restrict__ ad_)
{
    int idx = blockIdx.x * 256 + threadIdx.x;
    int row = idx >> 3, h = idx & 7;
    float s = 0.f, d = 0.f;
    #pragma unroll
    for (int j = 4 * h; j < 4 * h + 4; j++) {
        s += ASP[(size_t)j * MTOT + row];
        d += ADP[(size_t)j * MTOT + row];
    }
    as_[row * 8 + h] = s;
    ad_[row * 8 + h] = d;
}

// ---------------- int8 quantization of GAT features: warp per (node,head) ----------------
__global__ void __launch_bounds__(256) quant_h_k(
    const __half* __restrict__ hb, signed char* __restrict__ hq,
    float* __restrict__ hs)
{
    int nh   = blockIdx.x * 8 + (threadIdx.x >> 5);   // row of [MTOT*HH][256]
    int lane = threadIdx.x & 31;
    const float4* src = (const float4*)(hb + (size_t)nh * 256);  // 8 halves per float4
    float4 raw = src[lane];
    const __half2* h2 = (const __half2*)&raw;
    float f[8];
    #pragma unroll
    for (int i = 0; i < 4; i++) {
        float2 p = __half22float2(h2[i]);
        f[2 * i] = p.x; f[2 * i + 1] = p.y;
    }
    float m = 0.f;
    #pragma unroll
    for (int i = 0; i < 8; i++) m = fmaxf(m, fabsf(f[i]));
    #pragma unroll
    for (int o = 16; o; o >>= 1) m = fmaxf(m, __shfl_xor_sync(0xffffffffu, m, o));
    float inv = m > 0.f ? 127.f / m : 0.f;
    if (lane == 0) hs[nh] = m * (1.f / 127.f);
    int q[8];
    #pragma unroll
    for (int i = 0; i < 8; i++) {
        int v = __float2int_rn(f[i] * inv);
        q[i] = v > 127 ? 127 : (v < -127 ? -127 : v);
    }
    unsigned lo = (q[0] & 255) | ((q[1] & 255) << 8) | ((q[2] & 255) << 16) | ((unsigned)(q[3] & 255) << 24);
    unsigned hi = (q[4] & 255) | ((q[5] & 255) << 8) | ((q[6] & 255) << 16) | ((unsigned)(q[7] & 255) << 24);
    *(uint2*)(hq + (size_t)nh * 256 + lane * 8) = make_uint2(lo, hi);
}

// ---------------- sparse GAT aggregation (int8 features) ----------------
__global__ void __launch_bounds__(256) gat_agg_k(
    const signed char* __restrict__ hq, const float* __restrict__ hs,
    const float* __restrict__ as_, const float* __restrict__ ad_,
    const int* __restrict__ nbr, const int* __restrict__ cnt,
    const float* __restrict__ bias,
    float* __restrict__ y, __half* __restrict__ yh)
{
    __shared__ int   s_nbr[NBCAP];
    __shared__ float s_alpha[HH][NBCAP];
    __shared__ float s_inv[HH];
    __shared__ float4 s_red[4][64];
    int bt  = blockIdx.x;
    int b   = bt >> 10;
    int tid = threadIdx.x;
    int nc  = cnt[bt];
    for (int j = tid; j < nc; j += 256) s_nbr[j] = nbr[(size_t)bt * NBCAP + j];
    __syncthreads();

    for (int j = tid; j < nc; j += 256) {
        int s = s_nbr[j];
        const float* ap = as_ + (size_t)(b * NNODE + s) * HH;
        #pragma unroll
        for (int h = 0; h < HH; h++) {
            float e = ad_[bt * HH + h] + ap[h];
            e = e >= 0.f ? e : 0.2f * e;
            s_alpha[h][j] = __expf(e);
        }
    }
    __syncthreads();

    int wid = tid >> 5, lane = tid & 31;
    {
        float sum = 0.f;
        for (int j = lane; j < nc; j += 32) sum += s_alpha[wid][j];
        #pragma unroll
        for (int o = 16; o; o >>= 1) sum += __shfl_xor_sync(0xffffffffu, sum, o);
        if (lane == 0) s_inv[wid] = 1.f / (8.f * sum);
    }
    __syncthreads();
    for (int j = tid; j < nc; j += 256) {
        #pragma unroll
        for (int h = 0; h < HH; h++) s_alpha[h][j] *= s_inv[h];
    }
    __syncthreads();

    int hp = tid >> 6;          // 0..3 -> heads {2hp, 2hp+1}
    int h0 = hp * 2;
    int cg = tid & 63;
    int c4 = cg * 4;
    float a0 = 0.f, a1 = 0.f, a2 = 0.f, a3 = 0.f;
    for (int j = 0; j < nc; j++) {
        size_t nb = (size_t)(b * NNODE + s_nbr[j]);
        float2 sc = *(const float2*)(hs + nb * HH + h0);       // warp-broadcast
        float w0 = s_alpha[h0][j] * sc.x;
        float w1 = s_alpha[h0 + 1][j] * sc.y;
        const signed char* base = hq + nb * (HH * DD);
        char4 c0 = *(const char4*)(base + h0 * DD + c4);
        char4 c1 = *(const char4*)(base + (h0 + 1) * DD + c4);
        a0 = fmaf(w0, (float)c0.x, fmaf(w1, (float)c1.x, a0));
        a1 = fmaf(w0, (float)c0.y, fmaf(w1, (float)c1.y, a1));
        a2 = fmaf(w0, (float)c0.z, fmaf(w1, (float)c1.z, a2));
        a3 = fmaf(w0, (float)c0.w, fmaf(w1, (float)c1.w, a3));
    }
    s_red[hp][cg] = make_float4(a0, a1, a2, a3);
    __syncthreads();
    {
        int c = tid;
        const float* r0 = (const float*)&s_red[0][c >> 2];
        const float* r1 = (const float*)&s_red[1][c >> 2];
        const float* r2 = (const float*)&s_red[2][c >> 2];
        const float* r3 = (const float*)&s_red[3][c >> 2];
        int u = c & 3;
        float v = r0[u] + r1[u] + r2[u] + r3[u] + bias[c];
        y[(size_t)bt * DD + c] = v;
        yh[(size_t)bt * DD + c] = __float2half_rn(v);
    }
}

// ---------------- sparse masked attention (fp16 QKV) ----------------
__global__ void __launch_bounds__(256) attn_sparse_k(
    const __half* __restrict__ QKV, const int* __restrict__ nbr,
    const int* __restrict__ cnt, __half* __restrict__ Om)
{
    __shared__ int s_nbr[NBCAP];
    int bt  = blockIdx.x;
    int b   = bt >> 10;
    int tid = threadIdx.x;
    int nc  = cnt[bt];
    for (int j = tid; j < nc; j += 256) s_nbr[j] = nbr[(size_t)bt * NBCAP + j];
    __syncthreads();
    int h = tid >> 5, lane = tid & 31;
    const int LD3 = 3 * DD;
    float q = __half2float(QKV[(size_t)bt * LD3 + h * DHH + lane]) * 0.17677669529663687f;
    float accv = 0.f, accw = 0.f;
    int j = 0;
    for (; j + 4 <= nc; j += 4) {
        float d[4], vv[4];
        #pragma unroll
        for (int u = 0; u < 4; u++) {
            int s = s_nbr[j + u];
            size_t base = (size_t)(b * NNODE + s) * LD3 + h * DHH + lane;
            d[u]  = q * __half2float(QKV[base + DD]);
            vv[u] = __half2float(QKV[base + 2 * DD]);
        }
        #pragma unroll
        for (int o = 16; o; o >>= 1) {
            #pragma unroll
            for (int u = 0; u < 4; u++) d[u] += __shfl_xor_sync(0xffffffffu, d[u], o);
        }
        #pragma unroll
        for (int u = 0; u < 4; u++) {
            float w = __expf(d[u]);
            accv = fmaf(w, vv[u], accv);
            accw += w;
        }
    }
    for (; j < nc; j++) {
        int s = s_nbr[j];
        size_t base = (size_t)(b * NNODE + s) * LD3 + h * DHH + lane;
        float d = q * __half2float(QKV[base + DD]);
        float vvv = __half2float(QKV[base + 2 * DD]);
        #pragma unroll
        for (int o = 16; o; o >>= 1) d += __shfl_xor_sync(0xffffffffu, d, o);
        float w = __expf(d);
        accv = fmaf(w, vvv, accv);
        accw += w;
    }
    Om[(size_t)bt * LD3 + h * DHH + lane] = __float2half_rn(accv / accw);  // NOTE: see launch — AOH is compact [MTOT*DD]
}

// compact-output variant wrapper is below via ldc trick; keep simple: separate kernel
__global__ void __launch_bounds__(256) attn_sparse2_k(
    const __half* __restrict__ QKV, const int* __restrict__ nbr,
    const int* __restrict__ cnt, __half* __restrict__ Om)
{
    __shared__ int s_nbr[NBCAP];
    int bt  = blockIdx.x;
    int b   = bt >> 10;
    int tid = threadIdx.x;
    int nc  = cnt[bt];
    for (int j = tid; j < nc; j += 256) s_nbr[j] = nbr[(size_t)bt * NBCAP + j];
    __syncthreads();
    int h = tid >> 5, lane = tid & 31;
    const int LD3 = 3 * DD;
    float q = __half2float(QKV[(size_t)bt * LD3 + h * DHH + lane]) * 0.17677669529663687f;
    float accv = 0.f, accw = 0.f;
    int j = 0;
    for (; j + 4 <= nc; j += 4) {
        float d[4], vv[4];
        #pragma unroll
        for (int u = 0; u < 4; u++) {
            int s = s_nbr[j + u];
            size_t base = (size_t)(b * NNODE + s) * LD3 + h * DHH + lane;
            d[u]  = q * __half2float(QKV[base + DD]);
            vv[u] = __half2float(QKV[base + 2 * DD]);
        }
        #pragma unroll
        for (int o = 16; o; o >>= 1) {
            #pragma unroll
            for (int u = 0; u < 4; u++) d[u] += __shfl_xor_sync(0xffffffffu, d[u], o);
        }
        #pragma unroll
        for (int u = 0; u < 4; u++) {
            float w = __expf(d[u]);
            accv = fmaf(w, vv[u], accv);
            accw += w;
        }
    }
    for (; j < nc; j++) {
        int s = s_nbr[j];
        size_t base = (size_t)(b * NNODE + s) * LD3 + h * DHH + lane;
        float d = q * __half2float(QKV[base + DD]);
        float vvv = __half2float(QKV[base + 2 * DD]);
        #pragma unroll
        for (int o = 16; o; o >>= 1) d += __shfl_xor_sync(0xffffffffu, d, o);
        float w = __expf(d);
        accv = fmaf(w, vvv, accv);
        accw += w;
    }
    Om[(size_t)bt * DD + h * DHH + lane] = __float2half_rn(accv / accw);
}

// ---------------- layernorm: warp per row ----------------
template<int MODE, int WRITEH>
__global__ void __launch_bounds__(256) ln_warp_k(
    const float* __restrict__ a, const float* __restrict__ bsrc,
    const float* __restrict__ gam, const float* __restrict__ bet,
    float* __restrict__ out, __half* __restrict__ outh)
{
    int row  = blockIdx.x * 8 + (threadIdx.x >> 5);
    int lane = threadIdx.x & 31;
    size_t base = (size_t)row * DD;
    float v[8];
    float sum = 0.f;
    #pragma unroll
    for (int p = 0; p < 2; p++) {
        int c = lane * 4 + p * 128;
        float4 av = *(const float4*)(a + base + c);
        float4 bv = *(const float4*)(bsrc + base + c);
        if (MODE == 1) {
            bv.x = fmaxf(bv.x, 0.f); bv.y = fmaxf(bv.y, 0.f);
            bv.z = fmaxf(bv.z, 0.f); bv.w = fmaxf(bv.w, 0.f);
        }
        v[p*4+0] = av.x + bv.x; v[p*4+1] = av.y + bv.y;
        v[p*4+2] = av.z + bv.z; v[p*4+3] = av.w + bv.w;
        sum += v[p*4+0] + v[p*4+1] + v[p*4+2] + v[p*4+3];
    }
    #pragma unroll
    for (int o = 16; o; o >>= 1) sum += __shfl_xor_sync(0xffffffffu, sum, o);
    float mean = sum * (1.f / DD);
    float var = 0.f;
    #pragma unroll
    for (int i = 0; i < 8; i++) { float d = v[i] - mean; var += d * d; }
    #pragma unroll
    for (int o = 16; o; o >>= 1) var += __shfl_xor_sync(0xffffffffu, var, o);
    float rstd = rsqrtf(var * (1.f / DD) + 1e-5f);
    #pragma unroll
    for (int p = 0; p < 2; p++) {
        int c = lane * 4 + p * 128;
        float4 g = *(const float4*)(gam + c);
        float4 bb = *(const float4*)(bet + c);
        float4 o4;
        o4.x = (v[p*4+0] - mean) * rstd * g.x + bb.x;
        o4.y = (v[p*4+1] - mean) * rstd * g.y + bb.y;
        o4.z = (v[p*4+2] - mean) * rstd * g.z + bb.z;
        o4.w = (v[p*4+3] - mean) * rstd * g.w + bb.w;
        *(float4*)(out + base + c) = o4;
        if (WRITEH) {
            __half2 h0 = __floats2half2_rn(o4.x, o4.y);
            __half2 h1 = __floats2half2_rn(o4.z, o4.w);
            *(uint2*)(outh + base + c) = make_uint2(*(unsigned*)&h0, *(unsigned*)&h1);
        }
    }
}

extern "C" void kernel_launch(void* const* d_in, const int* in_sizes, int n_in,
                              void* d_out, int out_size)
{
    const float* emb  = (const float*)d_in[0];
    const int*   mask = (const int*)  d_in[2];
    const float* gatW = (const float*)d_in[4];
    const float* attS = (const float*)d_in[5];
    const float* attD = (const float*)d_in[6];
    const float* gatB = (const float*)d_in[7];
    const float* glnS = (const float*)d_in[8];
    const float* glnB = (const float*)d_in[9];
    const float* Wq = (const float*)d_in[10], *bq = (const float*)d_in[11];
    const float* Wk = (const float*)d_in[12], *bk = (const float*)d_in[13];
    const float* Wv = (const float*)d_in[14], *bv = (const float*)d_in[15];
    const float* Wo = (const float*)d_in[16], *bo = (const float*)d_in[17];
    const float* W1 = (const float*)d_in[18], *b1 = (const float*)d_in[19];
    const float* W2 = (const float*)d_in[20], *b2 = (const float*)d_in[21];
    const float* l1s = (const float*)d_in[22], *l1b = (const float*)d_in[23];
    const float* l2s = (const float*)d_in[24], *l2b = (const float*)d_in[25];
    float* out = (float*)d_out;

    float *XC,*AS,*AD,*ASP,*ADP,*BQKV,*Y,*HS;
    __half *XCH,*EMBH,*HBH,*QKVH,*WQKVH,*GATWH,*WOH,*W1H,*W2H,*AOH,*YH,*FFH;
    signed char* HQ;
    unsigned* BITS; int *NBR,*CNT;
    cudaGetSymbolAddress((void**)&XC, g_XC);
    cudaGetSymbolAddress((void**)&XCH, g_XCH);
    cudaGetSymbolAddress((void**)&EMBH, g_EMBH);
    cudaGetSymbolAddress((void**)&HBH, g_HBH);
    cudaGetSymbolAddress((void**)&HQ, g_HQ);
    cudaGetSymbolAddress((void**)&HS, g_HS);
    cudaGetSymbolAddress((void**)&AS, g_AS);
    cudaGetSymbolAddress((void**)&AD, g_AD);
    cudaGetSymbolAddress((void**)&ASP, g_ASP);
    cudaGetSymbolAddress((void**)&ADP, g_ADP);
    cudaGetSymbolAddress((void**)&QKVH, g_QKVH);
    cudaGetSymbolAddress((void**)&WQKVH, g_WQKVH);
    cudaGetSymbolAddress((void**)&BQKV, g_BQKV);
    cudaGetSymbolAddress((void**)&GATWH, g_GATWH);
    cudaGetSymbolAddress((void**)&WOH, g_WOH);
    cudaGetSymbolAddress((void**)&W1H, g_W1H);
    cudaGetSymbolAddress((void**)&W2H, g_W2H);
    cudaGetSymbolAddress((void**)&AOH, g_AOH);
    cudaGetSymbolAddress((void**)&Y,  g_Y);
    cudaGetSymbolAddress((void**)&YH, g_YH);
    cudaGetSymbolAddress((void**)&FFH, g_FFH);
    cudaGetSymbolAddress((void**)&BITS, g_BITS);
    cudaGetSymbolAddress((void**)&NBR, g_NBR);
    cudaGetSymbolAddress((void**)&CNT, g_CNT);

    const int M = MTOT;

    pack_adj_k<<<(BB*32*NNODE)/256, 256>>>(mask, BITS);
    build_nbr_k<<<(MTOT)/256, 256>>>(BITS, NBR, CNT);
    pack_qkv_k<<<(LTN*DD*3*DD + 255)/256, 256>>>(Wq, Wk, Wv, bq, bk, bv, WQKVH, BQKV);
    cvt_half_k<<<(MTOT*DD/4 + 255)/256, 256>>>(emb, EMBH, MTOT*DD);
    cvt_half_k<<<(LGN*HH*DD*DD/4 + 255)/256, 256>>>(gatW, GATWH, LGN*HH*DD*DD);
    cvt_half_k<<<(LTN*DD*DD/4 + 255)/256, 256>>>(Wo, WOH, LTN*DD*DD);
    cvt_half_k<<<(LTN*DD*DFFX/4 + 255)/256, 256>>>(W1, W1H, LTN*DD*DFFX);
    cvt_half_k<<<(LTN*DFFX*DD/4 + 255)/256, 256>>>(W2, W2H, LTN*DFFX*DD);

    // ---- GAT stack ----
    const __half* x = EMBH;
    for (int l = 0; l < LGN; l++) {
        hgemm_k<true,0,1,1><<<dim3((HH*DD)/128, M/128), 256>>>(
            M, HH*DD, DD, x, DD, GATWH + (size_t)l*HH*DD*DD, DD,
            HBH, HH*DD, nullptr, attS + l*HH*DD, attD + l*HH*DD, ASP, ADP);
        asad_reduce_k<<<(MTOT*8)/256, 256>>>(ASP, ADP, AS, AD);
        quant_h_k<<<MTOT, 256>>>(HBH, HQ, HS);
        gat_agg_k<<<M, 256>>>(HQ, HS, AS, AD, NBR, CNT, gatB + l*DD, Y, YH);
        x = YH;
    }
    ln_warp_k<1,1><<<M/8, 256>>>(emb, Y, glnS, glnB, XC, XCH);

    // ---- transformer layers ----
    for (int l = 0; l < LTN; l++) {
        hgemm_k<false,0,1,0><<<dim3((3*DD)/128, M/128), 256>>>(
            M, 3*DD, DD, XCH, DD, WQKVH + (size_t)l*DD*3*DD, 3*DD, QKVH, 3*DD,
            BQKV + l*3*DD, nullptr, nullptr, nullptr, nullptr);
        attn_sparse2_k<<<M, 256>>>(QKVH, NBR, CNT, AOH);
        hgemm_k<false,0,0,0><<<dim3(DD/128, M/128), 256>>>(
            M, DD, DD, AOH, DD, WOH + (size_t)l*DD*DD, DD, Y, DD,
            bo + l*DD, nullptr, nullptr, nullptr, nullptr);
        ln_warp_k<0,1><<<M/8, 256>>>(XC, Y, l1s + l*DD, l1b + l*DD, XC, XCH);
        hgemm_k<false,1,1,0><<<dim3(DFFX/128, M/128), 256>>>(
            M, DFFX, DD, XCH, DD, W1H + (size_t)l*DD*DFFX, DFFX, FFH, DFFX,
            b1 + l*DFFX, nullptr, nullptr, nullptr, nullptr);
        hgemm_k<false,0,0,0><<<dim3(DD/128, M/128), 256>>>(
            M, DD, DFFX, FFH, DFFX, W2H + (size_t)l*DFFX*DD, DD, Y, DD,
            b2 + l*DD, nullptr, nullptr, nullptr, nullptr);
        if (l == LTN - 1)
            ln_warp_k<0,0><<<M/8, 256>>>(XC, Y, l2s + l*DD, l2b + l*DD, out, nullptr);
        else
            ln_warp_k<0,1><<<M/8, 256>>>(XC, Y, l2s + l*DD, l2b + l*DD, XC, XCH);
    }
}

// round 8
// speedup vs baseline: 1.2108x; 1.2108x over previous
#include <cuda_runtime.h>
#include <cuda_fp16.h>
#include <math.h>

// ---------------- dims ----------------
#define BB    8
#define NNODE 1024
#define DD    256
#define HH    8
#define DHH   32
#define DFFX  1024
#define LGN   2
#define LTN   2
#define NBCAP 256
#define MTOT  (BB*NNODE)

// ---------------- scratch (device globals; no runtime allocation) ----------------
__device__ float                 g_XC[MTOT*DD];
__device__ __align__(16) __half  g_XCH[MTOT*DD];
__device__ __align__(16) __half  g_EMBH[MTOT*DD];
__device__ __align__(16) __half  g_HBH[MTOT*HH*DD];
__device__ float                 g_AS[MTOT*HH];
__device__ float                 g_AD[MTOT*HH];
__device__ float                 g_ASP[32*MTOT];
__device__ float                 g_ADP[32*MTOT];
__device__ __align__(16) __half  g_QKVH[MTOT*3*DD];
__device__ __align__(16) __half  g_WQKVH[LTN*DD*3*DD];
__device__ float                 g_BQKV[LTN*3*DD];
__device__ __align__(16) __half  g_GATWH[LGN*HH*DD*DD];
__device__ __align__(16) __half  g_WOH[LTN*DD*DD];
__device__ __align__(16) __half  g_W1H[LTN*DD*DFFX];
__device__ __align__(16) __half  g_W2H[LTN*DFFX*DD];
__device__ __align__(16) __half  g_AOH[MTOT*DD];
__device__ float                 g_Y [MTOT*DD];
__device__ __align__(16) __half  g_YH[MTOT*DD];
__device__ __align__(16) __half  g_FFH[MTOT*DFFX];
__device__ unsigned              g_BITS[MTOT*(NNODE/32)];
__device__ int                   g_NBR[MTOT*NBCAP];
__device__ int                   g_CNT[MTOT];

// ---------------- helpers ----------------
__device__ __forceinline__ void mma_f16(float* c, const unsigned* a, const unsigned* b) {
    asm volatile(
        "mma.sync.aligned.m16n8k16.row.col.f32.f16.f16.f32 "
        "{%0,%1,%2,%3}, {%4,%5,%6,%7}, {%8,%9}, {%0,%1,%2,%3};\n"
        : "+f"(c[0]), "+f"(c[1]), "+f"(c[2]), "+f"(c[3])
        : "r"(a[0]), "r"(a[1]), "r"(a[2]), "r"(a[3]), "r"(b[0]), "r"(b[1]));
}

__device__ __forceinline__ unsigned saddr(const void* p) {
    return (unsigned)__cvta_generic_to_shared(p);
}
__device__ __forceinline__ void cp16(unsigned dst, const void* src) {
    asm volatile("cp.async.cg.shared.global [%0], [%1], 16;\n" :: "r"(dst), "l"(src));
}
__device__ __forceinline__ void cp_commit() {
    asm volatile("cp.async.commit_group;\n" ::: "memory");
}
template<int N>
__device__ __forceinline__ void cp_wait() {
    asm volatile("cp.async.wait_group %0;\n" :: "n"(N) : "memory");
}
__device__ __forceinline__ void ldsm4(unsigned& r0, unsigned& r1, unsigned& r2, unsigned& r3,
                                      unsigned addr) {
    asm volatile("ldmatrix.sync.aligned.m8n8.x4.shared.b16 {%0,%1,%2,%3}, [%4];"
                 : "=r"(r0), "=r"(r1), "=r"(r2), "=r"(r3) : "r"(addr));
}
__device__ __forceinline__ void ldsm4t(unsigned& r0, unsigned& r1, unsigned& r2, unsigned& r3,
                                       unsigned addr) {
    asm volatile("ldmatrix.sync.aligned.m8n8.x4.trans.shared.b16 {%0,%1,%2,%3}, [%4];"
                 : "=r"(r0), "=r"(r1), "=r"(r2), "=r"(r3) : "r"(addr));
}

// ---------------- adjacency pack ----------------
__global__ void pack_adj_k(const int* __restrict__ mask, unsigned* __restrict__ bits) {
    int idx = blockIdx.x * blockDim.x + threadIdx.x;
    int t  = idx & (NNODE - 1);
    int sw = (idx >> 10) & 31;
    int b  = idx >> 15;
    const int* mp = mask + ((size_t)b * NNODE + (size_t)sw * 32) * NNODE + t;
    unsigned w = 0;
    #pragma unroll
    for (int i = 0; i < 32; i++)
        if (mp[(size_t)i * NNODE] > 0) w |= (1u << i);
    int s0 = sw * 32;
    if (t >= s0 && t < s0 + 32) w |= (1u << (t - s0));
    bits[(b * NNODE + t) * 32 + sw] = w;
}

// ---------------- neighbor list build ----------------
__global__ void build_nbr_k(const unsigned* __restrict__ bits,
                            int* __restrict__ nbr, int* __restrict__ cnt) {
    int bt = blockIdx.x * blockDim.x + threadIdx.x;
    if (bt >= MTOT) return;
    const unsigned* bw = bits + (size_t)bt * 32;
    int* np = nbr + (size_t)bt * NBCAP;
    int c = 0;
    #pragma unroll 4
    for (int w = 0; w < 32; w++) {
        unsigned m = bw[w];
        while (m) {
            int bit = __ffs(m) - 1;
            m &= m - 1;
            if (c < NBCAP) np[c] = w * 32 + bit;
            c++;
        }
    }
    cnt[bt] = c < NBCAP ? c : NBCAP;
}

// ---------------- generic fp32 -> fp16 convert ----------------
__global__ void cvt_half_k(const float* __restrict__ src, __half* __restrict__ dst, int n) {
    int i = blockIdx.x * 256 + threadIdx.x;
    if (i * 4 >= n) return;
    float4 v = *(const float4*)(src + i * 4);
    *(__half2*)(dst + i * 4)     = __floats2half2_rn(v.x, v.y);
    *(__half2*)(dst + i * 4 + 2) = __floats2half2_rn(v.z, v.w);
}

// ---------------- QKV pack ----------------
__global__ void pack_qkv_k(const float* __restrict__ Wq, const float* __restrict__ Wk,
                           const float* __restrict__ Wv, const float* __restrict__ bq,
                           const float* __restrict__ bk, const float* __restrict__ bv,
                           __half* __restrict__ W, float* __restrict__ Bb)
{
    int idx = blockIdx.x * 256 + threadIdx.x;
    if (idx >= LTN * DD * 3 * DD) return;
    int n = idx % (3 * DD);
    int k = (idx / (3 * DD)) % DD;
    int l = idx / (3 * DD * DD);
    float v;
    if (n < DD)            v = Wq[((size_t)l * DD + k) * DD + n];
    else if (n < 2 * DD)   v = Wk[((size_t)l * DD + k) * DD + n - DD];
    else                   v = Wv[((size_t)l * DD + k) * DD + n - 2 * DD];
    W[idx] = __float2half_rn(v);
    if (k == 0) {
        float bvv;
        if (n < DD)          bvv = bq[l * DD + n];
        else if (n < 2 * DD) bvv = bk[l * DD + n - DD];
        else                 bvv = bv[l * DD + n - 2 * DD];
        Bb[l * 3 * DD + n] = bvv;
    }
}

// ---------------- fp16 tensor-core GEMM: cp.async + ldmatrix ----------------
template<bool BT, int ACT, int HALF_OUT, int ASAD>
__global__ void __launch_bounds__(256) hgemm_k(
    int M, int Ncol, int K,
    const __half* __restrict__ A, int lda,
    const __half* __restrict__ B, int ldb,
    void* __restrict__ Cv, int ldc,
    const float* __restrict__ bias,
    const float* __restrict__ attS, const float* __restrict__ attD,
    float* __restrict__ ASP, float* __restrict__ ADP)
{
    __shared__ __align__(16) __half sA[2][128 * 24];
    __shared__ __align__(16) __half sB[2][3072];
    const int tid  = threadIdx.x;
    const int lane = tid & 31, wid = tid >> 5;
    const int wm = wid & 3, wn = wid >> 2;
    const int m0 = blockIdx.y * 128, n0 = blockIdx.x * 128;
    const int r = lane >> 2, cq = lane & 3;

    float acc[2][8][4];
    #pragma unroll
    for (int mt = 0; mt < 2; mt++)
        #pragma unroll
        for (int nt = 0; nt < 8; nt++)
            #pragma unroll
            for (int u = 0; u < 4; u++) acc[mt][nt][u] = 0.f;

    const int T = K / 16;

    auto loadT = [&](int st, int k0) {
        {
            int m = tid >> 1, c = tid & 1;
            cp16(saddr(&sA[st][m * 24 + c * 8]), A + (size_t)(m0 + m) * lda + k0 + c * 8);
        }
        if (BT) {
            int n = tid >> 1, c = tid & 1;
            cp16(saddr(&sB[st][n * 24 + c * 8]), B + (size_t)(n0 + n) * ldb + k0 + c * 8);
        } else {
            int kk = tid >> 4, c = tid & 15;
            cp16(saddr(&sB[st][kk * 136 + c * 8]), B + (size_t)(k0 + kk) * ldb + n0 + c * 8);
        }
        cp_commit();
    };

    loadT(0, 0);
    for (int t = 0; t < T; t++) {
        if (t + 1 < T) { loadT((t + 1) & 1, (t + 1) * 16); cp_wait<1>(); }
        else           { cp_wait<0>(); }
        __syncthreads();
        const int st = t & 1;

        unsigned af[2][4], bf[8][2];
        #pragma unroll
        for (int mt = 0; mt < 2; mt++) {
            int mrow = wm * 32 + mt * 16;
            unsigned addr = saddr(&sA[st][(mrow + (lane & 15)) * 24 + (lane >> 4) * 8]);
            ldsm4(af[mt][0], af[mt][1], af[mt][2], af[mt][3], addr);
        }
        #pragma unroll
        for (int p = 0; p < 4; p++) {
            int nb = wn * 64 + p * 16;
            if (BT) {
                int row = nb + (lane & 7) + ((lane >> 4) << 3);
                int col = ((lane >> 3) & 1) * 8;
                unsigned addr = saddr(&sB[st][row * 24 + col]);
                ldsm4(bf[2 * p][0], bf[2 * p][1], bf[2 * p + 1][0], bf[2 * p + 1][1], addr);
            } else {
                int krow = (lane & 7) + (((lane >> 3) & 1) << 3);
                int coln = nb + (lane >> 4) * 8;
                unsigned addr = saddr(&sB[st][krow * 136 + coln]);
                ldsm4t(bf[2 * p][0], bf[2 * p][1], bf[2 * p + 1][0], bf[2 * p + 1][1], addr);
            }
        }
        #pragma unroll
        for (int mt = 0; mt < 2; mt++)
            #pragma unroll
            for (int nt = 0; nt < 8; nt++)
                mma_f16(acc[mt][nt], af[mt], bf[nt]);
        __syncthreads();
    }

    if (ASAD) {
        float sS[2][2] = {{0,0},{0,0}}, sD[2][2] = {{0,0},{0,0}};
        #pragma unroll
        for (int mt = 0; mt < 2; mt++)
            #pragma unroll
            for (int nt = 0; nt < 8; nt++)
                #pragma unroll
                for (int u = 0; u < 4; u++) {
                    int g = n0 + wn * 64 + nt * 8 + cq * 2 + (u & 1);
                    float v = acc[mt][nt][u];
                    sS[mt][u >> 1] += v * attS[g];
                    sD[mt][u >> 1] += v * attD[g];
                }
        #pragma unroll
        for (int o = 1; o <= 2; o <<= 1)
            #pragma unroll
            for (int mt = 0; mt < 2; mt++)
                #pragma unroll
                for (int q = 0; q < 2; q++) {
                    sS[mt][q] += __shfl_xor_sync(0xffffffffu, sS[mt][q], o);
                    sD[mt][q] += __shfl_xor_sync(0xffffffffu, sD[mt][q], o);
                }
        if (cq == 0) {
            int j = (n0 >> 6) + wn;
            #pragma unroll
            for (int mt = 0; mt < 2; mt++)
                #pragma unroll
                for (int q = 0; q < 2; q++) {
                    int row = m0 + wm * 32 + mt * 16 + r + q * 8;
                    ASP[(size_t)j * M + row] = sS[mt][q];
                    ADP[(size_t)j * M + row] = sD[mt][q];
                }
        }
    }

    #pragma unroll
    for (int mt = 0; mt < 2; mt++) {
        int mrow = m0 + wm * 32 + mt * 16 + r;
        #pragma unroll
        for (int nt = 0; nt < 8; nt++) {
            int ncol = n0 + wn * 64 + nt * 8 + cq * 2;
            float* ac = acc[mt][nt];
            float2 v0 = make_float2(ac[0], ac[1]);
            float2 v1 = make_float2(ac[2], ac[3]);
            if (bias) {
                float b0 = bias[ncol], b1 = bias[ncol + 1];
                v0.x += b0; v0.y += b1; v1.x += b0; v1.y += b1;
            }
            if (ACT == 1) {
                v0.x = fmaxf(v0.x, 0.f); v0.y = fmaxf(v0.y, 0.f);
                v1.x = fmaxf(v1.x, 0.f); v1.y = fmaxf(v1.y, 0.f);
            }
            if (HALF_OUT) {
                __half* Ch = (__half*)Cv;
                *(__half2*)(Ch + (size_t)mrow * ldc + ncol) = __floats2half2_rn(v0.x, v0.y);
                *(__half2*)(Ch + (size_t)(mrow + 8) * ldc + ncol) = __floats2half2_rn(v1.x, v1.y);
            } else {
                float* Cf = (float*)Cv;
                *(float2*)(Cf + (size_t)mrow * ldc + ncol) = v0;
                *(float2*)(Cf + (size_t)(mrow + 8) * ldc + ncol) = v1;
            }
        }
    }
}

// ---------------- asad reduce ----------------
__global__ void asad_reduce_k(const float* __restrict__ ASP, const float* __restrict__ ADP,
                              float* __restrict__ as_, float* __restrict__ ad_)
{
    int idx = blockIdx.x * 256 + threadIdx.x;
    int row = idx >> 3, h = idx & 7;
    float s = 0.f, d = 0.f;
    #pragma unroll
    for (int j = 4 * h; j < 4 * h + 4; j++) {
        s += ASP[(size_t)j * MTOT + row];
        d += ADP[(size_t)j * MTOT + row];
    }
    as_[row * 8 + h] = s;
    ad_[row * 8 + h] = d;
}

// ---------------- sparse GAT aggregation (fp16; warp = head, lane = 8 cols) ----------------
__global__ void __launch_bounds__(256) gat_agg_k(
    const __half* __restrict__ hb, const float* __restrict__ as_,
    const float* __restrict__ ad_, const int* __restrict__ nbr,
    const int* __restrict__ cnt, const float* __restrict__ bias,
    float* __restrict__ y, __half* __restrict__ yh)
{
    __shared__ int   s_nbr[NBCAP];
    __shared__ float s_alpha[HH][NBCAP];
    __shared__ float s_inv[HH];
    __shared__ float s_red[HH][DD];
    int bt  = blockIdx.x;
    int b   = bt >> 10;
    int tid = threadIdx.x;
    int nc  = cnt[bt];
    for (int j = tid; j < nc; j += 256) s_nbr[j] = nbr[(size_t)bt * NBCAP + j];
    __syncthreads();

    // unnormalized weights
    for (int j = tid; j < nc; j += 256) {
        int s = s_nbr[j];
        const float* ap = as_ + (size_t)(b * NNODE + s) * HH;
        #pragma unroll
        for (int h = 0; h < HH; h++) {
            float e = ad_[bt * HH + h] + ap[h];
            e = e >= 0.f ? e : 0.2f * e;
            s_alpha[h][j] = __expf(e);
        }
    }
    __syncthreads();

    int h    = tid >> 5;       // warp = head
    int lane = tid & 31;
    {
        float sum = 0.f;
        for (int j = lane; j < nc; j += 32) sum += s_alpha[h][j];
        #pragma unroll
        for (int o = 16; o; o >>= 1) sum += __shfl_xor_sync(0xffffffffu, sum, o);
        if (lane == 0) s_inv[h] = 1.f / (8.f * sum);
    }
    __syncthreads();
    for (int j = tid; j < nc; j += 256) {
        #pragma unroll
        for (int hh = 0; hh < HH; hh++) s_alpha[hh][j] *= s_inv[hh];
    }
    __syncthreads();

    // gather: lane owns cols [lane*8, lane*8+8) of head h — 1 LDG.128 per edge
    const __half* hbase = hb + (size_t)b * NNODE * (HH * DD) + h * DD + lane * 8;
    float a[8];
    #pragma unroll
    for (int i = 0; i < 8; i++) a[i] = 0.f;
    #pragma unroll 2
    for (int j = 0; j < nc; j++) {
        float w = s_alpha[h][j];
        const float4* p = (const float4*)(hbase + (size_t)s_nbr[j] * (HH * DD));
        float4 raw = *p;
        const __half2* h2 = (const __half2*)&raw;
        #pragma unroll
        for (int i = 0; i < 4; i++) {
            float2 u = __half22float2(h2[i]);
            a[2 * i]     = fmaf(w, u.x, a[2 * i]);
            a[2 * i + 1] = fmaf(w, u.y, a[2 * i + 1]);
        }
    }
    #pragma unroll
    for (int i = 0; i < 8; i += 4)
        *(float4*)&s_red[h][lane * 8 + i] = make_float4(a[i], a[i+1], a[i+2], a[i+3]);
    __syncthreads();

    // sum over heads: thread c
    {
        int c = tid;
        float v = bias[c];
        #pragma unroll
        for (int hh = 0; hh < HH; hh++) v += s_red[hh][c];
        y[(size_t)bt * DD + c] = v;
        yh[(size_t)bt * DD + c] = __float2half_rn(v);
    }
}

// ---------------- sparse masked attention (fp16 QKV) ----------------
__global__ void __launch_bounds__(256) attn_sparse_k(
    const __half* __restrict__ QKV, const int* __restrict__ nbr,
    const int* __restrict__ cnt, __half* __restrict__ Om)
{
    __shared__ int s_nbr[NBCAP];
    int bt  = blockIdx.x;
    int b   = bt >> 10;
    int tid = threadIdx.x;
    int nc  = cnt[bt];
    for (int j = tid; j < nc; j += 256) s_nbr[j] = nbr[(size_t)bt * NBCAP + j];
    __syncthreads();
    int h = tid >> 5, lane = tid & 31;
    const int LD3 = 3 * DD;
    float q = __half2float(QKV[(size_t)bt * LD3 + h * DHH + lane]) * 0.17677669529663687f;
    float accv = 0.f, accw = 0.f;
    int j = 0;
    for (; j + 4 <= nc; j += 4) {
        float d[4], vv[4];
        #pragma unroll
        for (int u = 0; u < 4; u++) {
            int s = s_nbr[j + u];
            size_t base = (size_t)(b * NNODE + s) * LD3 + h * DHH + lane;
            d[u]  = q * __half2float(QKV[base + DD]);
            vv[u] = __half2float(QKV[base + 2 * DD]);
        }
        #pragma unroll
        for (int o = 16; o; o >>= 1) {
            #pragma unroll
            for (int u = 0; u < 4; u++) d[u] += __shfl_xor_sync(0xffffffffu, d[u], o);
        }
        #pragma unroll
        for (int u = 0; u < 4; u++) {
            float w = __expf(d[u]);
            accv = fmaf(w, vv[u], accv);
            accw += w;
        }
    }
    for (; j < nc; j++) {
        int s = s_nbr[j];
        size_t base = (size_t)(b * NNODE + s) * LD3 + h * DHH + lane;
        float d = q * __half2float(QKV[base + DD]);
        float vvv = __half2float(QKV[base + 2 * DD]);
        #pragma unroll
        for (int o = 16; o; o >>= 1) d += __shfl_xor_sync(0xffffffffu, d, o);
        float w = __expf(d);
        accv = fmaf(w, vvv, accv);
        accw += w;
    }
    Om[(size_t)bt * DD + h * DHH + lane] = __float2half_rn(accv / accw);
}

// ---------------- layernorm: warp per row ----------------
template<int MODE, int WRITEH>
__global__ void __launch_bounds__(256) ln_warp_k(
    const float* __restrict__ a, const float* __restrict__ bsrc,
    const float* __restrict__ gam, const float* __restrict__ bet,
    float* __restrict__ out, __half* __restrict__ outh)
{
    int row  = blockIdx.x * 8 + (threadIdx.x >> 5);
    int lane = threadIdx.x & 31;
    size_t base = (size_t)row * DD;
    float v[8];
    float sum = 0.f;
    #pragma unroll
    for (int p = 0; p < 2; p++) {
        int c = lane * 4 + p * 128;
        float4 av = *(const float4*)(a + base + c);
        float4 bv = *(const float4*)(bsrc + base + c);
        if (MODE == 1) {
            bv.x = fmaxf(bv.x, 0.f); bv.y = fmaxf(bv.y, 0.f);
            bv.z = fmaxf(bv.z, 0.f); bv.w = fmaxf(bv.w, 0.f);
        }
        v[p*4+0] = av.x + bv.x; v[p*4+1] = av.y + bv.y;
        v[p*4+2] = av.z + bv.z; v[p*4+3] = av.w + bv.w;
        sum += v[p*4+0] + v[p*4+1] + v[p*4+2] + v[p*4+3];
    }
    #pragma unroll
    for (int o = 16; o; o >>= 1) sum += __shfl_xor_sync(0xffffffffu, sum, o);
    float mean = sum * (1.f / DD);
    float var = 0.f;
    #pragma unroll
    for (int i = 0; i < 8; i++) { float d = v[i] - mean; var += d * d; }
    #pragma unroll
    for (int o = 16; o; o >>= 1) var += __shfl_xor_sync(0xffffffffu, var, o);
    float rstd = rsqrtf(var * (1.f / DD) + 1e-5f);
    #pragma unroll
    for (int p = 0; p < 2; p++) {
        int c = lane * 4 + p * 128;
        float4 g = *(const float4*)(gam + c);
        float4 bb = *(const float4*)(bet + c);
        float4 o4;
        o4.x = (v[p*4+0] - mean) * rstd * g.x + bb.x;
        o4.y = (v[p*4+1] - mean) * rstd * g.y + bb.y;
        o4.z = (v[p*4+2] - mean) * rstd * g.z + bb.z;
        o4.w = (v[p*4+3] - mean) * rstd * g.w + bb.w;
        *(float4*)(out + base + c) = o4;
        if (WRITEH) {
            __half2 h0 = __floats2half2_rn(o4.x, o4.y);
            __half2 h1 = __floats2half2_rn(o4.z, o4.w);
            *(uint2*)(outh + base + c) = make_uint2(*(unsigned*)&h0, *(unsigned*)&h1);
        }
    }
}

extern "C" void kernel_launch(void* const* d_in, const int* in_sizes, int n_in,
                              void* d_out, int out_size)
{
    const float* emb  = (const float*)d_in[0];
    const int*   mask = (const int*)  d_in[2];
    const float* gatW = (const float*)d_in[4];
    const float* attS = (const float*)d_in[5];
    const float* attD = (const float*)d_in[6];
    const float* gatB = (const float*)d_in[7];
    const float* glnS = (const float*)d_in[8];
    const float* glnB = (const float*)d_in[9];
    const float* Wq = (const float*)d_in[10], *bq = (const float*)d_in[11];
    const float* Wk = (const float*)d_in[12], *bk = (const float*)d_in[13];
    const float* Wv = (const float*)d_in[14], *bv = (const float*)d_in[15];
    const float* Wo = (const float*)d_in[16], *bo = (const float*)d_in[17];
    const float* W1 = (const float*)d_in[18], *b1 = (const float*)d_in[19];
    const float* W2 = (const float*)d_in[20], *b2 = (const float*)d_in[21];
    const float* l1s = (const float*)d_in[22], *l1b = (const float*)d_in[23];
    const float* l2s = (const float*)d_in[24], *l2b = (const float*)d_in[25];
    float* out = (float*)d_out;

    float *XC,*AS,*AD,*ASP,*ADP,*BQKV,*Y;
    __half *XCH,*EMBH,*HBH,*QKVH,*WQKVH,*GATWH,*WOH,*W1H,*W2H,*AOH,*YH,*FFH;
    unsigned* BITS; int *NBR,*CNT;
    cudaGetSymbolAddress((void**)&XC, g_XC);
    cudaGetSymbolAddress((void**)&XCH, g_XCH);
    cudaGetSymbolAddress((void**)&EMBH, g_EMBH);
    cudaGetSymbolAddress((void**)&HBH, g_HBH);
    cudaGetSymbolAddress((void**)&AS, g_AS);
    cudaGetSymbolAddress((void**)&AD, g_AD);
    cudaGetSymbolAddress((void**)&ASP, g_ASP);
    cudaGetSymbolAddress((void**)&ADP, g_ADP);
    cudaGetSymbolAddress((void**)&QKVH, g_QKVH);
    cudaGetSymbolAddress((void**)&WQKVH, g_WQKVH);
    cudaGetSymbolAddress((void**)&BQKV, g_BQKV);
    cudaGetSymbolAddress((void**)&GATWH, g_GATWH);
    cudaGetSymbolAddress((void**)&WOH, g_WOH);
    cudaGetSymbolAddress((void**)&W1H, g_W1H);
    cudaGetSymbolAddress((void**)&W2H, g_W2H);
    cudaGetSymbolAddress((void**)&AOH, g_AOH);
    cudaGetSymbolAddress((void**)&Y,  g_Y);
    cudaGetSymbolAddress((void**)&YH, g_YH);
    cudaGetSymbolAddress((void**)&FFH, g_FFH);
    cudaGetSymbolAddress((void**)&BITS, g_BITS);
    cudaGetSymbolAddress((void**)&NBR, g_NBR);
    cudaGetSymbolAddress((void**)&CNT, g_CNT);

    const int M = MTOT;

    pack_adj_k<<<(BB*32*NNODE)/256, 256>>>(mask, BITS);
    build_nbr_k<<<(MTOT)/256, 256>>>(BITS, NBR, CNT);
    pack_qkv_k<<<(LTN*DD*3*DD + 255)/256, 256>>>(Wq, Wk, Wv, bq, bk, bv, WQKVH, BQKV);
    cvt_half_k<<<(MTOT*DD/4 + 255)/256, 256>>>(emb, EMBH, MTOT*DD);
    cvt_half_k<<<(LGN*HH*DD*DD/4 + 255)/256, 256>>>(gatW, GATWH, LGN*HH*DD*DD);
    cvt_half_k<<<(LTN*DD*DD/4 + 255)/256, 256>>>(Wo, WOH, LTN*DD*DD);
    cvt_half_k<<<(LTN*DD*DFFX/4 + 255)/256, 256>>>(W1, W1H, LTN*DD*DFFX);
    cvt_half_k<<<(LTN*DFFX*DD/4 + 255)/256, 256>>>(W2, W2H, LTN*DFFX*DD);

    // ---- GAT stack ----
    const __half* x = EMBH;
    for (int l = 0; l < LGN; l++) {
        hgemm_k<true,0,1,1><<<dim3((HH*DD)/128, M/128), 256>>>(
            M, HH*DD, DD, x, DD, GATWH + (size_t)l*HH*DD*DD, DD,
            HBH, HH*DD, nullptr, attS + l*HH*DD, attD + l*HH*DD, ASP, ADP);
        asad_reduce_k<<<(MTOT*8)/256, 256>>>(ASP, ADP, AS, AD);
        gat_agg_k<<<M, 256>>>(HBH, AS, AD, NBR, CNT, gatB + l*DD, Y, YH);
        x = YH;
    }
    ln_warp_k<1,1><<<M/8, 256>>>(emb, Y, glnS, glnB, XC, XCH);

    // ---- transformer layers ----
    for (int l = 0; l < LTN; l++) {
        hgemm_k<false,0,1,0><<<dim3((3*DD)/128, M/128), 256>>>(
            M, 3*DD, DD, XCH, DD, WQKVH + (size_t)l*DD*3*DD, 3*DD, QKVH, 3*DD,
            BQKV + l*3*DD, nullptr, nullptr, nullptr, nullptr);
        attn_sparse_k<<<M, 256>>>(QKVH, NBR, CNT, AOH);
        hgemm_k<false,0,0,0><<<dim3(DD/128, M/128), 256>>>(
            M, DD, DD, AOH, DD, WOH + (size_t)l*DD*DD, DD, Y, DD,
            bo + l*DD, nullptr, nullptr, nullptr, nullptr);
        ln_warp_k<0,1><<<M/8, 256>>>(XC, Y, l1s + l*DD, l1b + l*DD, XC, XCH);
        hgemm_k<false,1,1,0><<<dim3(DFFX/128, M/128), 256>>>(
            M, DFFX, DD, XCH, DD, W1H + (size_t)l*DD*DFFX, DFFX, FFH, DFFX,
            b1 + l*DFFX, nullptr, nullptr, nullptr, nullptr);
        hgemm_k<false,0,0,0><<<dim3(DD/128, M/128), 256>>>(
            M, DD, DFFX, FFH, DFFX, W2H + (size_t)l*DFFX*DD, DD, Y, DD,
            b2 + l*DD, nullptr, nullptr, nullptr, nullptr);
        if (l == LTN - 1)
            ln_warp_k<0,0><<<M/8, 256>>>(XC, Y, l2s + l*DD, l2b + l*DD, out, nullptr);
        else
            ln_warp_k<0,1><<<M/8, 256>>>(XC, Y, l2s + l*DD, l2b + l*DD, XC, XCH);
    }
}